// round 15
// baseline (speedup 1.0000x reference)
#include <cuda_runtime.h>
#include <cuda_fp16.h>
#include <cuda_bf16.h>
#include <cstdint>
#include <cstddef>

// Problem constants
#define Bb   2
#define Ss   2048
#define Hh   2048
#define NHh  16
#define HDd  128
#define Pp   2048
#define Mm   (Bb * Ss)          // 4096 rows
#define H2   (Hh / 2)           // 1024
#define QKW  (2 * Pp)           // 4096 (qk row width)
#define MW16 (NHh * HDd)        // 2048 (fp16 q/k buffer row width)
#define EPSc 1e-6f

// ---------------- scratch (static device globals; no allocation) ----------------
__device__ float g_y1[(size_t)Mm * H2];
__device__ float g_lfout[(size_t)Mm * Hh];
__device__ __half g_hs16[(size_t)Mm * Hh];
__device__ __half g_wv16[(size_t)Pp * Hh];
__device__ __half g_wqk16[(size_t)QKW * Hh];
__device__ __half g_wo16[(size_t)Hh * Pp];
__device__ __half g_w1a16[(size_t)H2 * Hh];
__device__ __half g_w1b16[(size_t)H2 * Hh];
__device__ __half g_w2a16[(size_t)Hh * H2];
__device__ __half g_w2b16[(size_t)Hh * H2];
__device__ __half g_y1h[(size_t)Mm * H2];
__device__ __half g_lf16[(size_t)Mm * Hh];
__device__ __half g_v16[(size_t)Mm * Pp];
__device__ __half g_attn16[(size_t)Mm * Pp];
__device__ __half g_lf1c16[(size_t)Bb * Hh];
__device__ __half g_lf2c16[(size_t)Bb * H2];
__device__ __half g_qhi[(size_t)Mm * MW16];
__device__ __half g_qlo[(size_t)Mm * MW16];
__device__ __half g_khi[(size_t)Mm * MW16];
__device__ __half g_klo[(size_t)Mm * MW16];

// ---------------- helpers ----------------
__device__ __forceinline__ void mma_f16(float* d, const uint32_t* a, const uint32_t* b) {
    asm volatile(
        "mma.sync.aligned.m16n8k16.row.col.f32.f16.f16.f32 "
        "{%0,%1,%2,%3},{%4,%5,%6,%7},{%8,%9},{%0,%1,%2,%3};"
        : "+f"(d[0]), "+f"(d[1]), "+f"(d[2]), "+f"(d[3])
        : "r"(a[0]), "r"(a[1]), "r"(a[2]), "r"(a[3]), "r"(b[0]), "r"(b[1]));
}

__device__ __forceinline__ void ldsm4(uint32_t* r, uint32_t saddr) {
    asm volatile("ldmatrix.sync.aligned.m8n8.x4.shared.b16 {%0,%1,%2,%3}, [%4];"
        : "=r"(r[0]), "=r"(r[1]), "=r"(r[2]), "=r"(r[3]) : "r"(saddr));
}

__device__ __forceinline__ void ldsm4t(uint32_t* r, uint32_t saddr) {
    asm volatile("ldmatrix.sync.aligned.m8n8.x4.trans.shared.b16 {%0,%1,%2,%3}, [%4];"
        : "=r"(r[0]), "=r"(r[1]), "=r"(r[2]), "=r"(r[3]) : "r"(saddr));
}

__device__ __forceinline__ uint32_t h2pack(float lo, float hi) {
    __half2 h = __floats2half2_rn(lo, hi);
    return *reinterpret_cast<uint32_t*>(&h);
}

__device__ __forceinline__ void cp16(uint32_t* smem, const void* g) {
    uint32_t s = (uint32_t)__cvta_generic_to_shared(smem);
    asm volatile("cp.async.ca.shared.global [%0], [%1], 16;" :: "r"(s), "l"(g));
}

// ---------------- fp32 -> fp16 conversion ----------------
__global__ void cvt16_kernel(const float* __restrict__ in, __half* __restrict__ out, int n)
{
    int i = (blockIdx.x * 256 + threadIdx.x) * 8;
    if (i < n) {
        float4 f0 = *(const float4*)(in + i);
        float4 f1 = *(const float4*)(in + i + 4);
        uint4 u;
        u.x = h2pack(f0.x, f0.y); u.y = h2pack(f0.z, f0.w);
        u.z = h2pack(f1.x, f1.y); u.w = h2pack(f1.z, f1.w);
        *(uint4*)(out + i) = u;
    }
}

// ---------------- deinterleave conv weights -> fp16 ----------------
__global__ void deint16_kernel(const float* __restrict__ in, __half* __restrict__ a,
                               __half* __restrict__ b, int n)
{
    int i = blockIdx.x * 256 + threadIdx.x;
    if (i < n) {
        a[i] = __float2half_rn(in[2 * i]);
        b[i] = __float2half_rn(in[2 * i + 1]);
    }
}

// ========== FP16 tensor-core GEMM (NT), cp.async 4-stage pipeline + ldmatrix ==========
// Optional fused RoPE epilogue (freqs != nullptr): BN=128 column block == one
// half-head (pure q or pure k); tile staged to smem fp32, RoPE applied with the
// exact arithmetic of the old rope2 kernel, written as fp16 hi/lo.
#define BMh 128
#define BNh 128
#define BKh 32
#define PWH 20
#define NSTG 4
#define STG_W (BMh * PWH)
#define GH_SMEM (NSTG * STG_W * 2 * 4)         // 81920 bytes
#define RPP 132                                 // rope staging pitch (fp32 words)

__global__ __launch_bounds__(256, 2) void gemm_h16_kernel(
    const __half* __restrict__ A, const __half* __restrict__ W,
    const __half* __restrict__ A2, const __half* __restrict__ W2,
    float* __restrict__ C, __half* __restrict__ C16,
    int N, int K, const float* __restrict__ bias,
    const __half* __restrict__ shiftCache,
    const float* __restrict__ freqs, const int* __restrict__ positions,
    __half* __restrict__ qhi_g, __half* __restrict__ qlo_g,
    __half* __restrict__ khi_g, __half* __restrict__ klo_g)
{
    extern __shared__ uint32_t sh[];
    uint32_t* Abase = sh;
    uint32_t* Bbase = sh + NSTG * STG_W;
    const uint32_t sb4 = (uint32_t)__cvta_generic_to_shared(sh);

    const int tid = threadIdx.x;
    const int lane = tid & 31;
    const int warp = tid >> 5;
    const int wm = warp >> 2;
    const int wn = warp & 3;
    const int bm = blockIdx.y * BMh;
    const int bn = blockIdx.x * BNh;
    const int mBase = wm * 64;
    const int nBase = wn * 32;

    const int ra = tid >> 1;
    const int seg = tid & 1;
    const int sk = seg * 16;
    const int sw = seg * 8;

    const __half* arow;
    {
        int m = bm + ra;
        if (shiftCache) {
            arow = (m % Ss == 0) ? (shiftCache + (size_t)(m / Ss) * K)
                                 : (A + (size_t)(m - 1) * K);
        } else {
            arow = A + (size_t)m * K;
        }
    }
    const __half* wrow  = W + (size_t)(bn + ra) * K;
    const __half* a2row = A2 ? (A2 + (size_t)(bm + ra) * K) : nullptr;
    const __half* w2row = W2 ? (W2 + (size_t)(bn + ra) * K) : nullptr;

    float acc[4][4][4];
#pragma unroll
    for (int mi = 0; mi < 4; mi++)
#pragma unroll
        for (int ni = 0; ni < 4; ni++)
#pragma unroll
            for (int e = 0; e < 4; e++) acc[mi][ni][e] = 0.f;

    const int nk = K / BKh;
    const int nkt = A2 ? (2 * nk) : nk;

    auto issue = [&](int kt) {
        const __half* ap;
        const __half* wp;
        if (kt < nk) { ap = arow  + kt * BKh + sk;        wp = wrow  + kt * BKh + sk; }
        else         { ap = a2row + (kt - nk) * BKh + sk; wp = w2row + (kt - nk) * BKh + sk; }
        uint32_t* as = Abase + (kt % NSTG) * STG_W + ra * PWH + sw;
        uint32_t* bs = Bbase + (kt % NSTG) * STG_W + ra * PWH + sw;
        cp16(as,     ap);
        cp16(as + 4, ap + 8);
        cp16(bs,     wp);
        cp16(bs + 4, wp + 8);
    };

#pragma unroll
    for (int s = 0; s < NSTG - 1; s++) {
        if (s < nkt) issue(s);
        asm volatile("cp.async.commit_group;");
    }

    const int row4 = lane >> 2;
    const int col4 = lane & 3;
    const int lane15 = lane & 15;
    const int lhi4 = (lane >> 4) << 2;

    const uint32_t aoff_l = ((mBase + lane15) * PWH + lhi4) * 4;
    const uint32_t boff_l = ((nBase + lane15) * PWH + lhi4) * 4;
    const uint32_t Bbase_b = (uint32_t)(NSTG * STG_W * 4);

    for (int kt = 0; kt < nkt; kt++) {
        asm volatile("cp.async.wait_group %0;" :: "n"(NSTG - 2));
        __syncthreads();

        if (kt + NSTG - 1 < nkt) issue(kt + NSTG - 1);
        asm volatile("cp.async.commit_group;");

        const uint32_t stg = (uint32_t)((kt % NSTG) * STG_W * 4);
        const uint32_t aS = sb4 + stg + aoff_l;
        const uint32_t bS = sb4 + Bbase_b + stg + boff_l;
#pragma unroll
        for (int kw = 0; kw < 16; kw += 8) {
            uint32_t af[4][4], bp[2][4];
#pragma unroll
            for (int mi = 0; mi < 4; mi++)
                ldsm4(af[mi], aS + (mi * 16 * PWH + kw) * 4);
#pragma unroll
            for (int nia = 0; nia < 2; nia++)
                ldsm4(bp[nia], bS + (nia * 16 * PWH + kw) * 4);
#pragma unroll
            for (int nia = 0; nia < 2; nia++) {
                uint32_t b0[2] = {bp[nia][0], bp[nia][2]};
                uint32_t b1[2] = {bp[nia][1], bp[nia][3]};
#pragma unroll
                for (int mi = 0; mi < 4; mi++) {
                    mma_f16(acc[mi][2 * nia],     af[mi], b0);
                    mma_f16(acc[mi][2 * nia + 1], af[mi], b1);
                }
            }
        }
    }

    if (freqs) {
        // ---- fused RoPE epilogue (arithmetic identical to old rope2 kernel) ----
        __syncthreads();                      // done reading stage buffers
        float* S = (float*)sh;                // 128 x RPP fp32 staging
#pragma unroll
        for (int mi = 0; mi < 4; mi++) {
            int rl = mBase + mi * 16 + row4;
#pragma unroll
            for (int ni = 0; ni < 4; ni++) {
                int cl = nBase + ni * 8 + 2 * col4;
                S[rl * RPP + cl]           = acc[mi][ni][0];
                S[rl * RPP + cl + 1]       = acc[mi][ni][1];
                S[(rl + 8) * RPP + cl]     = acc[mi][ni][2];
                S[(rl + 8) * RPP + cl + 1] = acc[mi][ni][3];
            }
        }
        __syncthreads();

        const int rl = tid >> 1;              // local row 0..127
        const int sg = tid & 1;               // d segment: [sg*32, sg*32+32)
        const int m = bm + rl;
        const int pos = positions[m];
        const int hh = bn >> 8;               // head
        const bool isK = (bn & 255) >= 128;
        const float scale = 0.08838834764831845f;

        uint32_t h1p[16], l1p[16], h2p[16], l2p[16];
#pragma unroll
        for (int j2 = 0; j2 < 16; j2++) {
            float r1v[2], r2v[2];
#pragma unroll
            for (int u = 0; u < 2; u++) {
                int d = sg * 32 + j2 * 2 + u;
                float x1 = S[rl * RPP + d];
                float x2 = S[rl * RPP + d + 64];
                float f1 = freqs[(size_t)pos * HDd + d];
                float f2 = freqs[(size_t)pos * HDd + d + 64];
                float c1 = cosf(f1), s1 = sinf(f1);
                float c2 = cosf(f2), s2 = sinf(f2);
                float r1 = x1 * c1 - x2 * s1;
                float r2 = x2 * c2 + x1 * s2;
                if (!isK) { r1 *= scale; r2 *= scale; }
                r1v[u] = r1; r2v[u] = r2;
            }
            __half a0 = __float2half_rn(r1v[0]);
            __half a1 = __float2half_rn(r1v[1]);
            __half b0 = __float2half_rn(r2v[0]);
            __half b1 = __float2half_rn(r2v[1]);
            h1p[j2] = ((uint32_t)*(uint16_t*)&a0) | ((uint32_t)*(uint16_t*)&a1 << 16);
            h2p[j2] = ((uint32_t)*(uint16_t*)&b0) | ((uint32_t)*(uint16_t*)&b1 << 16);
            __half c0 = __float2half_rn(r1v[0] - __half2float(a0));
            __half c1h = __float2half_rn(r1v[1] - __half2float(a1));
            __half d0 = __float2half_rn(r2v[0] - __half2float(b0));
            __half d1 = __float2half_rn(r2v[1] - __half2float(b1));
            l1p[j2] = ((uint32_t)*(uint16_t*)&c0) | ((uint32_t)*(uint16_t*)&c1h << 16);
            l2p[j2] = ((uint32_t)*(uint16_t*)&d0) | ((uint32_t)*(uint16_t*)&d1 << 16);
        }

        __half* hiDst = isK ? khi_g : qhi_g;
        __half* loDst = isK ? klo_g : qlo_g;
        size_t o1 = (size_t)m * MW16 + (size_t)hh * HDd + sg * 32;
        size_t o2 = o1 + 64;
#pragma unroll
        for (int c = 0; c < 4; c++) {
            *(uint4*)(hiDst + o1 + c * 8) = *(uint4*)&h1p[c * 4];
            *(uint4*)(loDst + o1 + c * 8) = *(uint4*)&l1p[c * 4];
            *(uint4*)(hiDst + o2 + c * 8) = *(uint4*)&h2p[c * 4];
            *(uint4*)(loDst + o2 + c * 8) = *(uint4*)&l2p[c * 4];
        }
        return;
    }

#pragma unroll
    for (int mi = 0; mi < 4; mi++) {
        int r = bm + mBase + mi * 16 + row4;
#pragma unroll
        for (int ni = 0; ni < 4; ni++) {
            int cb = bn + nBase + ni * 8 + 2 * col4;
            float2 b2 = make_float2(0.f, 0.f);
            if (bias) { b2.x = bias[cb]; b2.y = bias[cb + 1]; }
            float2 v0 = make_float2(acc[mi][ni][0] + b2.x, acc[mi][ni][1] + b2.y);
            float2 v1 = make_float2(acc[mi][ni][2] + b2.x, acc[mi][ni][3] + b2.y);
            if (C) {
                *(float2*)(C + (size_t)r * N + cb) = v0;
                *(float2*)(C + (size_t)(r + 8) * N + cb) = v1;
            }
            if (C16) {
                *(uint32_t*)(C16 + (size_t)r * N + cb) = h2pack(v0.x, v0.y);
                *(uint32_t*)(C16 + (size_t)(r + 8) * N + cb) = h2pack(v1.x, v1.y);
            }
        }
    }
}

// ---------------- residual add + RMSNorm -> fp16 output ----------------
__global__ __launch_bounds__(256) void rmsnorm_kernel(
    const float* __restrict__ y2, const float* __restrict__ x,
    const float* __restrict__ w, __half* __restrict__ out16)
{
    int m = blockIdx.x;
    const float* yrow = y2 + (size_t)m * Hh;
    const float* xrow = x + (size_t)m * Hh;

    float ss = 0.f;
    for (int i = threadIdx.x; i < Hh; i += 256) {
        float t = yrow[i] + xrow[i];
        ss += t * t;
    }
#pragma unroll
    for (int off = 16; off > 0; off >>= 1)
        ss += __shfl_xor_sync(0xffffffffu, ss, off);

    __shared__ float red[9];
    int lane = threadIdx.x & 31, wid = threadIdx.x >> 5;
    if (lane == 0) red[wid] = ss;
    __syncthreads();
    if (threadIdx.x == 0) {
        float tot = 0.f;
        for (int i = 0; i < 8; i++) tot += red[i];
        red[8] = rsqrtf(tot / (float)Hh + EPSc);
    }
    __syncthreads();
    float inv = red[8];
    __half* orow = out16 + (size_t)m * Hh;
    for (int i = threadIdx.x; i < Hh; i += 256) {
        float t = (yrow[i] + xrow[i]) * w[i] * inv;
        orow[i] = __float2half_rn(t);
    }
}

// ---------------- fp16 tensor-core causal flash attention (ldmatrix) ----------------
#define F2Q 128
#define F2K 32
#define PQ 68
#define PV 20
#define Q_SZ (F2Q * PQ)
#define K_SZ (F2K * PQ)
#define P_SZ (F2Q * PV)
#define F2_SMEM ((2 * Q_SZ + 3 * K_SZ + P_SZ) * 4)   // 105984 bytes

__global__ __launch_bounds__(256, 2) void flash2_kernel(
    const __half* __restrict__ qhi_g, const __half* __restrict__ qlo_g,
    const __half* __restrict__ khi_g, const __half* __restrict__ klo_g,
    const __half* __restrict__ v16, __half* __restrict__ attn16)
{
    extern __shared__ uint32_t fsm[];
    uint32_t* Qhi = fsm;
    uint32_t* Qlo = Qhi + Q_SZ;
    uint32_t* Khi = Qlo + Q_SZ;
    uint32_t* Klo = Khi + K_SZ;
    uint32_t* Vr  = Klo + K_SZ;
    uint32_t* Ps  = Vr  + K_SZ;
    const uint32_t sb4 = (uint32_t)__cvta_generic_to_shared(fsm);

    const int qt = gridDim.x - 1 - blockIdx.x;
    const int h  = blockIdx.y;
    const int b  = blockIdx.z;
    const int q0 = qt * F2Q;
    const int tid  = threadIdx.x;
    const int lane = tid & 31;
    const int warp = tid >> 5;
    const int wm16 = warp * 16;
    const int row4 = lane >> 2;
    const int col4 = lane & 3;
    const int lane15 = lane & 15;
    const int lhi4 = (lane >> 4) << 2;
    const int bS = b * Ss;
    const int hq = h * HDd;

    for (int c = tid; c < F2Q * 16; c += 256) {
        int row = c >> 4, ch = c & 15;
        size_t g = (size_t)(bS + q0 + row) * MW16 + hq + ch * 8;
        cp16(Qhi + row * PQ + ch * 4, qhi_g + g);
        cp16(Qlo + row * PQ + ch * 4, qlo_g + g);
    }
    asm volatile("cp.async.commit_group;");

    const uint32_t qa_hi = sb4 + (((wm16 + lane15) * PQ + lhi4)) * 4;
    const uint32_t qa_lo = qa_hi + Q_SZ * 4;
    const uint32_t ka_hi = sb4 + (2 * Q_SZ + lane15 * PQ + lhi4) * 4;
    const uint32_t ka_lo = ka_hi + K_SZ * 4;
    const uint32_t va    = sb4 + (2 * Q_SZ + 2 * K_SZ) * 4
                         + (uint32_t)(lane15 * PQ) * 4 + ((lane >> 4) << 4);
    const uint32_t pa_a  = sb4 + (2 * Q_SZ + 3 * K_SZ) * 4
                         + (((wm16 + lane15) * PV + lhi4)) * 4;

    float O[16][4];
#pragma unroll
    for (int ni = 0; ni < 16; ni++)
#pragma unroll
        for (int e = 0; e < 4; e++) O[ni][e] = 0.f;
    float mrow0 = -1e30f, mrow1 = -1e30f, lrow0 = 0.f, lrow1 = 0.f;

    const int kend = q0 + F2Q;
    for (int j0 = 0; j0 < kend; j0 += F2K) {
        __syncthreads();
        for (int c = tid; c < F2K * 16; c += 256) {
            int row = c >> 4, ch = c & 15;
            size_t g = (size_t)(bS + j0 + row) * MW16 + hq + ch * 8;
            cp16(Khi + row * PQ + ch * 4, khi_g + g);
            cp16(Klo + row * PQ + ch * 4, klo_g + g);
            cp16(Vr  + row * PQ + ch * 4,
                 v16 + (size_t)(bS + j0 + row) * Pp + hq + ch * 8);
        }
        asm volatile("cp.async.commit_group;");
        asm volatile("cp.async.wait_group 0;");
        __syncthreads();

        bool active = (j0 <= q0 + wm16 + 15);
        if (active) {
            float s[4][4];
#pragma unroll
            for (int ni = 0; ni < 4; ni++)
#pragma unroll
                for (int e = 0; e < 4; e++) s[ni][e] = 0.f;

#pragma unroll
            for (int kw = 0; kw < 64; kw += 8) {
                uint32_t ahi[4], alo[4];
                ldsm4(ahi, qa_hi + kw * 4);
                ldsm4(alo, qa_lo + kw * 4);
#pragma unroll
                for (int nia = 0; nia < 2; nia++) {
                    uint32_t bh[4], bl[4];
                    ldsm4(bh, ka_hi + (nia * 16 * PQ + kw) * 4);
                    ldsm4(bl, ka_lo + (nia * 16 * PQ + kw) * 4);
                    uint32_t bh0[2] = {bh[0], bh[2]}, bh1[2] = {bh[1], bh[3]};
                    uint32_t bl0[2] = {bl[0], bl[2]}, bl1[2] = {bl[1], bl[3]};
                    mma_f16(s[2 * nia],     ahi, bh0);
                    mma_f16(s[2 * nia],     alo, bh0);
                    mma_f16(s[2 * nia],     ahi, bl0);
                    mma_f16(s[2 * nia + 1], ahi, bh1);
                    mma_f16(s[2 * nia + 1], alo, bh1);
                    mma_f16(s[2 * nia + 1], ahi, bl1);
                }
            }

            if (j0 + F2K - 1 > q0 + wm16) {
                int qlo_i = q0 + wm16 + row4;
                int qhi_i = qlo_i + 8;
#pragma unroll
                for (int ni = 0; ni < 4; ni++) {
                    int kp = j0 + ni * 8 + 2 * col4;
                    if (kp     > qlo_i) s[ni][0] = -1e30f;
                    if (kp + 1 > qlo_i) s[ni][1] = -1e30f;
                    if (kp     > qhi_i) s[ni][2] = -1e30f;
                    if (kp + 1 > qhi_i) s[ni][3] = -1e30f;
                }
            }

            float mx0 = -1e30f, mx1 = -1e30f;
#pragma unroll
            for (int ni = 0; ni < 4; ni++) {
                mx0 = fmaxf(mx0, fmaxf(s[ni][0], s[ni][1]));
                mx1 = fmaxf(mx1, fmaxf(s[ni][2], s[ni][3]));
            }
            mx0 = fmaxf(mx0, __shfl_xor_sync(0xffffffffu, mx0, 1));
            mx0 = fmaxf(mx0, __shfl_xor_sync(0xffffffffu, mx0, 2));
            mx1 = fmaxf(mx1, __shfl_xor_sync(0xffffffffu, mx1, 1));
            mx1 = fmaxf(mx1, __shfl_xor_sync(0xffffffffu, mx1, 2));
            float mn0 = fmaxf(mrow0, mx0), mn1 = fmaxf(mrow1, mx1);
            float al0 = __expf(mrow0 - mn0), al1 = __expf(mrow1 - mn1);
            mrow0 = mn0; mrow1 = mn1;

            float sum0 = 0.f, sum1 = 0.f;
            int pb0 = (wm16 + row4) * PV;
            int pb1 = (wm16 + row4 + 8) * PV;
#pragma unroll
            for (int ni = 0; ni < 4; ni++) {
                float p0 = __expf(s[ni][0] - mn0);
                float p1 = __expf(s[ni][1] - mn0);
                float p2 = __expf(s[ni][2] - mn1);
                float p3 = __expf(s[ni][3] - mn1);
                sum0 += p0 + p1; sum1 += p2 + p3;
                Ps[pb0 + ni * 4 + col4] = h2pack(p0, p1);
                Ps[pb1 + ni * 4 + col4] = h2pack(p2, p3);
            }
            lrow0 = lrow0 * al0 + sum0;
            lrow1 = lrow1 * al1 + sum1;
#pragma unroll
            for (int ni = 0; ni < 16; ni++) {
                O[ni][0] *= al0; O[ni][1] *= al0;
                O[ni][2] *= al1; O[ni][3] *= al1;
            }
            __syncwarp();

#pragma unroll
            for (int kvs = 0; kvs < 2; kvs++) {
                uint32_t a[4];
                ldsm4(a, pa_a + kvs * 8 * 4);
                uint32_t vrow = va + (uint32_t)(kvs * 16 * PQ) * 4;
#pragma unroll
                for (int nia = 0; nia < 8; nia++) {
                    uint32_t bv[4];
                    ldsm4t(bv, vrow + nia * 32);
                    mma_f16(O[2 * nia],     a, &bv[0]);
                    mma_f16(O[2 * nia + 1], a, &bv[2]);
                }
            }
        }
    }

    lrow0 += __shfl_xor_sync(0xffffffffu, lrow0, 1);
    lrow0 += __shfl_xor_sync(0xffffffffu, lrow0, 2);
    lrow1 += __shfl_xor_sync(0xffffffffu, lrow1, 1);
    lrow1 += __shfl_xor_sync(0xffffffffu, lrow1, 2);
    float inv0 = 1.f / lrow0, inv1 = 1.f / lrow1;

    size_t ob0 = (size_t)(bS + q0 + wm16 + row4) * Pp + hq;
    size_t ob1 = ob0 + (size_t)8 * Pp;
#pragma unroll
    for (int ni = 0; ni < 16; ni++) {
        int cb = ni * 8 + 2 * col4;
        *(uint32_t*)(attn16 + ob0 + cb) = h2pack(O[ni][0] * inv0, O[ni][1] * inv0);
        *(uint32_t*)(attn16 + ob1 + cb) = h2pack(O[ni][2] * inv1, O[ni][3] * inv1);
    }
}

// ---------------- tail outputs ----------------
__global__ void tails_kernel(const float* __restrict__ hs, const float* __restrict__ y1,
                             float* __restrict__ out)
{
    int i = blockIdx.x * 256 + threadIdx.x;
    size_t off1 = (size_t)Mm * Hh;
    size_t off2 = off1 + (size_t)Bb * Hh;
    if (i < Bb * Hh) {
        int b = i / Hh, hh = i % Hh;
        out[off1 + i] = hs[((size_t)b * Ss + (Ss - 1)) * Hh + hh];
    }
    if (i < Bb * H2) {
        int b = i / H2, oo = i % H2;
        out[off2 + i] = y1[((size_t)b * Ss + (Ss - 1)) * H2 + oo];
    }
}

// ---------------- launch ----------------
extern "C" void kernel_launch(void* const* d_in, const int* in_sizes, int n_in,
                              void* d_out, int out_size)
{
    (void)in_sizes; (void)n_in; (void)out_size;
    const float* hs      = (const float*)d_in[0];
    const float* freqs   = (const float*)d_in[1];
    const int*   pos     = (const int*)  d_in[2];
    const float* Wqk     = (const float*)d_in[3];
    const float* Wv      = (const float*)d_in[4];
    const float* Wo      = (const float*)d_in[5];
    const float* conv1_w = (const float*)d_in[6];
    const float* conv1_b = (const float*)d_in[7];
    const float* conv2_w = (const float*)d_in[8];
    const float* conv2_b = (const float*)d_in[9];
    const float* ln_w    = (const float*)d_in[10];
    const float* lf1c    = (const float*)d_in[11];
    const float* lf2c    = (const float*)d_in[12];
    float* out = (float*)d_out;

    float *y1, *lfout;
    __half *hs16, *wv16, *wqk16, *wo16, *w1a16, *w1b16, *w2a16, *w2b16;
    __half *y1h, *lf16, *v16, *attn16, *lf1c16, *lf2c16;
    __half *qhi, *qlo, *khi, *klo;
    cudaGetSymbolAddress((void**)&y1,     g_y1);
    cudaGetSymbolAddress((void**)&lfout,  g_lfout);
    cudaGetSymbolAddress((void**)&hs16,   g_hs16);
    cudaGetSymbolAddress((void**)&wv16,   g_wv16);
    cudaGetSymbolAddress((void**)&wqk16,  g_wqk16);
    cudaGetSymbolAddress((void**)&wo16,   g_wo16);
    cudaGetSymbolAddress((void**)&w1a16,  g_w1a16);
    cudaGetSymbolAddress((void**)&w1b16,  g_w1b16);
    cudaGetSymbolAddress((void**)&w2a16,  g_w2a16);
    cudaGetSymbolAddress((void**)&w2b16,  g_w2b16);
    cudaGetSymbolAddress((void**)&y1h,    g_y1h);
    cudaGetSymbolAddress((void**)&lf16,   g_lf16);
    cudaGetSymbolAddress((void**)&v16,    g_v16);
    cudaGetSymbolAddress((void**)&attn16, g_attn16);
    cudaGetSymbolAddress((void**)&lf1c16, g_lf1c16);
    cudaGetSymbolAddress((void**)&lf2c16, g_lf2c16);
    cudaGetSymbolAddress((void**)&qhi,    g_qhi);
    cudaGetSymbolAddress((void**)&qlo,    g_qlo);
    cudaGetSymbolAddress((void**)&khi,    g_khi);
    cudaGetSymbolAddress((void**)&klo,    g_klo);

    static bool attr_done = false;
    if (!attr_done) {
        cudaFuncSetAttribute(flash2_kernel,
                             cudaFuncAttributeMaxDynamicSharedMemorySize, F2_SMEM);
        cudaFuncSetAttribute(gemm_h16_kernel,
                             cudaFuncAttributeMaxDynamicSharedMemorySize, GH_SMEM);
        attr_done = true;
    }

    // 1) fp16 operand prep
    cvt16_kernel<<<(Mm * Hh / 8 + 255) / 256, 256>>>(hs, hs16, Mm * Hh);
    cvt16_kernel<<<(Pp * Hh / 8 + 255) / 256, 256>>>(Wv, wv16, Pp * Hh);
    cvt16_kernel<<<(QKW * Hh / 8 + 255) / 256, 256>>>(Wqk, wqk16, QKW * Hh);
    cvt16_kernel<<<(Hh * Pp / 8 + 255) / 256, 256>>>(Wo, wo16, Hh * Pp);
    cvt16_kernel<<<(Bb * Hh / 8 + 255) / 256, 256>>>(lf1c, lf1c16, Bb * Hh);
    cvt16_kernel<<<(Bb * H2 / 8 + 255) / 256, 256>>>(lf2c, lf2c16, Bb * H2);
    deint16_kernel<<<(H2 * Hh + 255) / 256, 256>>>(conv1_w, w1a16, w1b16, H2 * Hh);
    deint16_kernel<<<(Hh * H2 + 255) / 256, 256>>>(conv2_w, w2a16, w2b16, Hh * H2);

    // 2) v16 = hs @ Wv^T  (fp16 only)
    gemm_h16_kernel<<<dim3(Pp / BNh, Mm / BMh), 256, GH_SMEM>>>(
        hs16, wv16, nullptr, nullptr, nullptr, v16, Pp, Hh, nullptr, nullptr,
        nullptr, nullptr, nullptr, nullptr, nullptr, nullptr);

    // 3) y1 = shift(hs) @ w1a^T + hs @ w1b^T + b1  (fp32 + fp16 mirror)
    gemm_h16_kernel<<<dim3(H2 / BNh, Mm / BMh), 256, GH_SMEM>>>(
        hs16, w1a16, hs16, w1b16, y1, y1h, H2, Hh, conv1_b, lf1c16,
        nullptr, nullptr, nullptr, nullptr, nullptr, nullptr);

    // 4) y2 = shift(y1) @ w2a^T + y1 @ w2b^T + b2
    gemm_h16_kernel<<<dim3(Hh / BNh, Mm / BMh), 256, GH_SMEM>>>(
        y1h, w2a16, y1h, w2b16, lfout, nullptr, Hh, H2, conv2_b, lf2c16,
        nullptr, nullptr, nullptr, nullptr, nullptr, nullptr);

    // 5) lf16 = rmsnorm(y2 + hs) * ln_w
    rmsnorm_kernel<<<Mm, 256>>>(lfout, hs, ln_w, lf16);

    // 6+7) qk GEMM with fused RoPE epilogue -> qhi/qlo/khi/klo (fp16)
    gemm_h16_kernel<<<dim3(QKW / BNh, Mm / BMh), 256, GH_SMEM>>>(
        lf16, wqk16, nullptr, nullptr, nullptr, nullptr, QKW, Hh, nullptr, nullptr,
        freqs, pos, qhi, qlo, khi, klo);

    // 8) fp16 flash attention -> attn16
    flash2_kernel<<<dim3(Ss / F2Q, NHh, Bb), 256, F2_SMEM>>>(
        qhi, qlo, khi, klo, v16, attn16);

    // 9) output = attn16 @ Wo^T  (fp32 out)
    gemm_h16_kernel<<<dim3(Hh / BNh, Mm / BMh), 256, GH_SMEM>>>(
        attn16, wo16, nullptr, nullptr, out, nullptr, Hh, Pp, nullptr, nullptr,
        nullptr, nullptr, nullptr, nullptr, nullptr, nullptr);

    // 10) tails
    tails_kernel<<<(Bb * Hh + 255) / 256, 256>>>(hs, y1, out);
}

// round 16
// speedup vs baseline: 1.0825x; 1.0825x over previous
#include <cuda_runtime.h>
#include <cuda_fp16.h>
#include <cuda_bf16.h>
#include <cstdint>
#include <cstddef>

// Problem constants
#define Bb   2
#define Ss   2048
#define Hh   2048
#define NHh  16
#define HDd  128
#define Pp   2048
#define MAXP 4096
#define Mm   (Bb * Ss)          // 4096 rows
#define H2   (Hh / 2)           // 1024
#define QKW  (2 * Pp)           // 4096 (qk row width)
#define MW16 (NHh * HDd)        // 2048 (fp16 q/k buffer row width)
#define EPSc 1e-6f

// ---------------- scratch (static device globals; no allocation) ----------------
__device__ float g_y1[(size_t)Mm * H2];
__device__ float g_lfout[(size_t)Mm * Hh];
__device__ float g_qk[(size_t)Mm * QKW];
__device__ float g_cosT[(size_t)MAXP * HDd];
__device__ float g_sinT[(size_t)MAXP * HDd];
__device__ __half g_hs16[(size_t)Mm * Hh];
__device__ __half g_wv16[(size_t)Pp * Hh];
__device__ __half g_wqk16[(size_t)QKW * Hh];
__device__ __half g_wo16[(size_t)Hh * Pp];
__device__ __half g_w1a16[(size_t)H2 * Hh];
__device__ __half g_w1b16[(size_t)H2 * Hh];
__device__ __half g_w2a16[(size_t)Hh * H2];
__device__ __half g_w2b16[(size_t)Hh * H2];
__device__ __half g_y1h[(size_t)Mm * H2];
__device__ __half g_lf16[(size_t)Mm * Hh];
__device__ __half g_v16[(size_t)Mm * Pp];
__device__ __half g_attn16[(size_t)Mm * Pp];
__device__ __half g_lf1c16[(size_t)Bb * Hh];
__device__ __half g_lf2c16[(size_t)Bb * H2];
__device__ __half g_qhi[(size_t)Mm * MW16];
__device__ __half g_qlo[(size_t)Mm * MW16];
__device__ __half g_khi[(size_t)Mm * MW16];
__device__ __half g_klo[(size_t)Mm * MW16];

// ---------------- helpers ----------------
__device__ __forceinline__ void mma_f16(float* d, const uint32_t* a, const uint32_t* b) {
    asm volatile(
        "mma.sync.aligned.m16n8k16.row.col.f32.f16.f16.f32 "
        "{%0,%1,%2,%3},{%4,%5,%6,%7},{%8,%9},{%0,%1,%2,%3};"
        : "+f"(d[0]), "+f"(d[1]), "+f"(d[2]), "+f"(d[3])
        : "r"(a[0]), "r"(a[1]), "r"(a[2]), "r"(a[3]), "r"(b[0]), "r"(b[1]));
}

__device__ __forceinline__ void ldsm4(uint32_t* r, uint32_t saddr) {
    asm volatile("ldmatrix.sync.aligned.m8n8.x4.shared.b16 {%0,%1,%2,%3}, [%4];"
        : "=r"(r[0]), "=r"(r[1]), "=r"(r[2]), "=r"(r[3]) : "r"(saddr));
}

__device__ __forceinline__ void ldsm4t(uint32_t* r, uint32_t saddr) {
    asm volatile("ldmatrix.sync.aligned.m8n8.x4.trans.shared.b16 {%0,%1,%2,%3}, [%4];"
        : "=r"(r[0]), "=r"(r[1]), "=r"(r[2]), "=r"(r[3]) : "r"(saddr));
}

__device__ __forceinline__ uint32_t h2pack(float lo, float hi) {
    __half2 h = __floats2half2_rn(lo, hi);
    return *reinterpret_cast<uint32_t*>(&h);
}

__device__ __forceinline__ void cp16(uint32_t* smem, const void* g) {
    uint32_t s = (uint32_t)__cvta_generic_to_shared(smem);
    asm volatile("cp.async.ca.shared.global [%0], [%1], 16;" :: "r"(s), "l"(g));
}

// ---------------- fp32 -> fp16 conversion ----------------
__global__ void cvt16_kernel(const float* __restrict__ in, __half* __restrict__ out, int n)
{
    int i = (blockIdx.x * 256 + threadIdx.x) * 8;
    if (i < n) {
        float4 f0 = *(const float4*)(in + i);
        float4 f1 = *(const float4*)(in + i + 4);
        uint4 u;
        u.x = h2pack(f0.x, f0.y); u.y = h2pack(f0.z, f0.w);
        u.z = h2pack(f1.x, f1.y); u.w = h2pack(f1.z, f1.w);
        *(uint4*)(out + i) = u;
    }
}

// ---------------- deinterleave conv weights -> fp16 ----------------
__global__ void deint16_kernel(const float* __restrict__ in, __half* __restrict__ a,
                               __half* __restrict__ b, int n)
{
    int i = blockIdx.x * 256 + threadIdx.x;
    if (i < n) {
        a[i] = __float2half_rn(in[2 * i]);
        b[i] = __float2half_rn(in[2 * i + 1]);
    }
}

// ---------------- one-time cos/sin LUT over freqs ----------------
__global__ __launch_bounds__(256) void sctab_kernel(
    const float* __restrict__ freqs, float* __restrict__ cosT, float* __restrict__ sinT)
{
    int i = blockIdx.x * 256 + threadIdx.x;   // MAXP*HDd total
    float f = freqs[i];
    cosT[i] = cosf(f);
    sinT[i] = sinf(f);
}

// ========== FP16 tensor-core GEMM (NT), cp.async 4-stage pipeline + ldmatrix ==========
#define BMh 128
#define BNh 128
#define BKh 32
#define PWH 20
#define NSTG 4
#define STG_W (BMh * PWH)
#define GH_SMEM (NSTG * STG_W * 2 * 4)         // 81920 bytes

__global__ __launch_bounds__(256, 2) void gemm_h16_kernel(
    const __half* __restrict__ A, const __half* __restrict__ W,
    const __half* __restrict__ A2, const __half* __restrict__ W2,
    float* __restrict__ C, __half* __restrict__ C16,
    int N, int K, const float* __restrict__ bias,
    const __half* __restrict__ shiftCache)
{
    extern __shared__ uint32_t sh[];
    uint32_t* Abase = sh;
    uint32_t* Bbase = sh + NSTG * STG_W;
    const uint32_t sb4 = (uint32_t)__cvta_generic_to_shared(sh);

    const int tid = threadIdx.x;
    const int lane = tid & 31;
    const int warp = tid >> 5;
    const int wm = warp >> 2;
    const int wn = warp & 3;
    const int bm = blockIdx.y * BMh;
    const int bn = blockIdx.x * BNh;
    const int mBase = wm * 64;
    const int nBase = wn * 32;

    const int ra = tid >> 1;
    const int seg = tid & 1;
    const int sk = seg * 16;
    const int sw = seg * 8;

    const __half* arow;
    {
        int m = bm + ra;
        if (shiftCache) {
            arow = (m % Ss == 0) ? (shiftCache + (size_t)(m / Ss) * K)
                                 : (A + (size_t)(m - 1) * K);
        } else {
            arow = A + (size_t)m * K;
        }
    }
    const __half* wrow  = W + (size_t)(bn + ra) * K;
    const __half* a2row = A2 ? (A2 + (size_t)(bm + ra) * K) : nullptr;
    const __half* w2row = W2 ? (W2 + (size_t)(bn + ra) * K) : nullptr;

    float acc[4][4][4];
#pragma unroll
    for (int mi = 0; mi < 4; mi++)
#pragma unroll
        for (int ni = 0; ni < 4; ni++)
#pragma unroll
            for (int e = 0; e < 4; e++) acc[mi][ni][e] = 0.f;

    const int nk = K / BKh;
    const int nkt = A2 ? (2 * nk) : nk;

    auto issue = [&](int kt) {
        const __half* ap;
        const __half* wp;
        if (kt < nk) { ap = arow  + kt * BKh + sk;        wp = wrow  + kt * BKh + sk; }
        else         { ap = a2row + (kt - nk) * BKh + sk; wp = w2row + (kt - nk) * BKh + sk; }
        uint32_t* as = Abase + (kt % NSTG) * STG_W + ra * PWH + sw;
        uint32_t* bs = Bbase + (kt % NSTG) * STG_W + ra * PWH + sw;
        cp16(as,     ap);
        cp16(as + 4, ap + 8);
        cp16(bs,     wp);
        cp16(bs + 4, wp + 8);
    };

#pragma unroll
    for (int s = 0; s < NSTG - 1; s++) {
        if (s < nkt) issue(s);
        asm volatile("cp.async.commit_group;");
    }

    const int row4 = lane >> 2;
    const int col4 = lane & 3;
    const int lane15 = lane & 15;
    const int lhi4 = (lane >> 4) << 2;

    const uint32_t aoff_l = ((mBase + lane15) * PWH + lhi4) * 4;
    const uint32_t boff_l = ((nBase + lane15) * PWH + lhi4) * 4;
    const uint32_t Bbase_b = (uint32_t)(NSTG * STG_W * 4);

    for (int kt = 0; kt < nkt; kt++) {
        asm volatile("cp.async.wait_group %0;" :: "n"(NSTG - 2));
        __syncthreads();

        if (kt + NSTG - 1 < nkt) issue(kt + NSTG - 1);
        asm volatile("cp.async.commit_group;");

        const uint32_t stg = (uint32_t)((kt % NSTG) * STG_W * 4);
        const uint32_t aS = sb4 + stg + aoff_l;
        const uint32_t bS = sb4 + Bbase_b + stg + boff_l;
#pragma unroll
        for (int kw = 0; kw < 16; kw += 8) {
            uint32_t af[4][4], bp[2][4];
#pragma unroll
            for (int mi = 0; mi < 4; mi++)
                ldsm4(af[mi], aS + (mi * 16 * PWH + kw) * 4);
#pragma unroll
            for (int nia = 0; nia < 2; nia++)
                ldsm4(bp[nia], bS + (nia * 16 * PWH + kw) * 4);
#pragma unroll
            for (int nia = 0; nia < 2; nia++) {
                uint32_t b0[2] = {bp[nia][0], bp[nia][2]};
                uint32_t b1[2] = {bp[nia][1], bp[nia][3]};
#pragma unroll
                for (int mi = 0; mi < 4; mi++) {
                    mma_f16(acc[mi][2 * nia],     af[mi], b0);
                    mma_f16(acc[mi][2 * nia + 1], af[mi], b1);
                }
            }
        }
    }

#pragma unroll
    for (int mi = 0; mi < 4; mi++) {
        int r = bm + mBase + mi * 16 + row4;
#pragma unroll
        for (int ni = 0; ni < 4; ni++) {
            int cb = bn + nBase + ni * 8 + 2 * col4;
            float2 b2 = make_float2(0.f, 0.f);
            if (bias) { b2.x = bias[cb]; b2.y = bias[cb + 1]; }
            float2 v0 = make_float2(acc[mi][ni][0] + b2.x, acc[mi][ni][1] + b2.y);
            float2 v1 = make_float2(acc[mi][ni][2] + b2.x, acc[mi][ni][3] + b2.y);
            if (C) {
                *(float2*)(C + (size_t)r * N + cb) = v0;
                *(float2*)(C + (size_t)(r + 8) * N + cb) = v1;
            }
            if (C16) {
                *(uint32_t*)(C16 + (size_t)r * N + cb) = h2pack(v0.x, v0.y);
                *(uint32_t*)(C16 + (size_t)(r + 8) * N + cb) = h2pack(v1.x, v1.y);
            }
        }
    }
}

// ---------------- residual add + RMSNorm -> fp16 output ----------------
__global__ __launch_bounds__(256) void rmsnorm_kernel(
    const float* __restrict__ y2, const float* __restrict__ x,
    const float* __restrict__ w, __half* __restrict__ out16)
{
    int m = blockIdx.x;
    const float* yrow = y2 + (size_t)m * Hh;
    const float* xrow = x + (size_t)m * Hh;

    float ss = 0.f;
    for (int i = threadIdx.x; i < Hh; i += 256) {
        float t = yrow[i] + xrow[i];
        ss += t * t;
    }
#pragma unroll
    for (int off = 16; off > 0; off >>= 1)
        ss += __shfl_xor_sync(0xffffffffu, ss, off);

    __shared__ float red[9];
    int lane = threadIdx.x & 31, wid = threadIdx.x >> 5;
    if (lane == 0) red[wid] = ss;
    __syncthreads();
    if (threadIdx.x == 0) {
        float tot = 0.f;
        for (int i = 0; i < 8; i++) tot += red[i];
        red[8] = rsqrtf(tot / (float)Hh + EPSc);
    }
    __syncthreads();
    float inv = red[8];
    __half* orow = out16 + (size_t)m * Hh;
    for (int i = threadIdx.x; i < Hh; i += 256) {
        float t = (yrow[i] + xrow[i]) * w[i] * inv;
        orow[i] = __float2half_rn(t);
    }
}

// ---------------- RoPE v3: LUT-based, vectorized -> fp16 hi/lo buffers ----------------
// One block per row m; thread -> (head, q/k) slot + 8 contiguous d-values.
__global__ __launch_bounds__(256) void rope3_kernel(
    const float* __restrict__ qkbuf,
    const float* __restrict__ cosT, const float* __restrict__ sinT,
    const int* __restrict__ positions,
    __half* __restrict__ qhi, __half* __restrict__ qlo,
    __half* __restrict__ khi, __half* __restrict__ klo)
{
    const int m = blockIdx.x;
    const int p = positions[m];
    const int tid = threadIdx.x;
    const int slot = tid >> 3;          // 0..31
    const int hh = slot >> 1;
    const int isK = slot & 1;
    const int dc = (tid & 7) << 3;      // 0..56 step 8

    const float* src = qkbuf + (size_t)m * QKW + hh * 256 + isK * 128 + dc;
    const float* tc = cosT + (size_t)p * HDd + dc;
    const float* ts = sinT + (size_t)p * HDd + dc;

    float x1[8], x2[8], c1[8], s1[8], c2[8], s2[8];
    *(float4*)&x1[0] = *(const float4*)(src);
    *(float4*)&x1[4] = *(const float4*)(src + 4);
    *(float4*)&x2[0] = *(const float4*)(src + 64);
    *(float4*)&x2[4] = *(const float4*)(src + 68);
    *(float4*)&c1[0] = *(const float4*)(tc);
    *(float4*)&c1[4] = *(const float4*)(tc + 4);
    *(float4*)&s1[0] = *(const float4*)(ts);
    *(float4*)&s1[4] = *(const float4*)(ts + 4);
    *(float4*)&c2[0] = *(const float4*)(tc + 64);
    *(float4*)&c2[4] = *(const float4*)(tc + 68);
    *(float4*)&s2[0] = *(const float4*)(ts + 64);
    *(float4*)&s2[4] = *(const float4*)(ts + 68);

    const float scale = 0.08838834764831845f;   // 1/sqrt(128)
    uint32_t h1p[4], l1p[4], h2p[4], l2p[4];
#pragma unroll
    for (int j = 0; j < 4; j++) {
        float r1a, r1b, r2a, r2b;
        {
            int u = 2 * j;
            float ra = x1[u] * c1[u] - x2[u] * s1[u];
            float rb = x1[u+1] * c1[u+1] - x2[u+1] * s1[u+1];
            float rc = x2[u] * c2[u] + x1[u] * s2[u];
            float rd = x2[u+1] * c2[u+1] + x1[u+1] * s2[u+1];
            if (!isK) { ra *= scale; rb *= scale; rc *= scale; rd *= scale; }
            r1a = ra; r1b = rb; r2a = rc; r2b = rd;
        }
        __half a0 = __float2half_rn(r1a), a1 = __float2half_rn(r1b);
        __half b0 = __float2half_rn(r2a), b1 = __float2half_rn(r2b);
        h1p[j] = ((uint32_t)*(uint16_t*)&a0) | ((uint32_t)*(uint16_t*)&a1 << 16);
        h2p[j] = ((uint32_t)*(uint16_t*)&b0) | ((uint32_t)*(uint16_t*)&b1 << 16);
        __half c0 = __float2half_rn(r1a - __half2float(a0));
        __half c1h = __float2half_rn(r1b - __half2float(a1));
        __half d0 = __float2half_rn(r2a - __half2float(b0));
        __half d1 = __float2half_rn(r2b - __half2float(b1));
        l1p[j] = ((uint32_t)*(uint16_t*)&c0) | ((uint32_t)*(uint16_t*)&c1h << 16);
        l2p[j] = ((uint32_t)*(uint16_t*)&d0) | ((uint32_t)*(uint16_t*)&d1 << 16);
    }

    __half* hiD = isK ? khi : qhi;
    __half* loD = isK ? klo : qlo;
    size_t o1 = (size_t)m * MW16 + (size_t)hh * HDd + dc;
    *(uint4*)(hiD + o1)      = *(uint4*)h1p;
    *(uint4*)(loD + o1)      = *(uint4*)l1p;
    *(uint4*)(hiD + o1 + 64) = *(uint4*)h2p;
    *(uint4*)(loD + o1 + 64) = *(uint4*)l2p;
}

// ---------------- fp16 tensor-core causal flash attention (ldmatrix) ----------------
#define F2Q 128
#define F2K 32
#define PQ 68
#define PV 20
#define Q_SZ (F2Q * PQ)
#define K_SZ (F2K * PQ)
#define P_SZ (F2Q * PV)
#define F2_SMEM ((2 * Q_SZ + 3 * K_SZ + P_SZ) * 4)   // 105984 bytes

__global__ __launch_bounds__(256, 2) void flash2_kernel(
    const __half* __restrict__ qhi_g, const __half* __restrict__ qlo_g,
    const __half* __restrict__ khi_g, const __half* __restrict__ klo_g,
    const __half* __restrict__ v16, __half* __restrict__ attn16)
{
    extern __shared__ uint32_t fsm[];
    uint32_t* Qhi = fsm;
    uint32_t* Qlo = Qhi + Q_SZ;
    uint32_t* Khi = Qlo + Q_SZ;
    uint32_t* Klo = Khi + K_SZ;
    uint32_t* Vr  = Klo + K_SZ;
    uint32_t* Ps  = Vr  + K_SZ;
    const uint32_t sb4 = (uint32_t)__cvta_generic_to_shared(fsm);

    const int qt = gridDim.x - 1 - blockIdx.x;
    const int h  = blockIdx.y;
    const int b  = blockIdx.z;
    const int q0 = qt * F2Q;
    const int tid  = threadIdx.x;
    const int lane = tid & 31;
    const int warp = tid >> 5;
    const int wm16 = warp * 16;
    const int row4 = lane >> 2;
    const int col4 = lane & 3;
    const int lane15 = lane & 15;
    const int lhi4 = (lane >> 4) << 2;
    const int bS = b * Ss;
    const int hq = h * HDd;

    for (int c = tid; c < F2Q * 16; c += 256) {
        int row = c >> 4, ch = c & 15;
        size_t g = (size_t)(bS + q0 + row) * MW16 + hq + ch * 8;
        cp16(Qhi + row * PQ + ch * 4, qhi_g + g);
        cp16(Qlo + row * PQ + ch * 4, qlo_g + g);
    }
    asm volatile("cp.async.commit_group;");

    const uint32_t qa_hi = sb4 + (((wm16 + lane15) * PQ + lhi4)) * 4;
    const uint32_t qa_lo = qa_hi + Q_SZ * 4;
    const uint32_t ka_hi = sb4 + (2 * Q_SZ + lane15 * PQ + lhi4) * 4;
    const uint32_t ka_lo = ka_hi + K_SZ * 4;
    const uint32_t va    = sb4 + (2 * Q_SZ + 2 * K_SZ) * 4
                         + (uint32_t)(lane15 * PQ) * 4 + ((lane >> 4) << 4);
    const uint32_t pa_a  = sb4 + (2 * Q_SZ + 3 * K_SZ) * 4
                         + (((wm16 + lane15) * PV + lhi4)) * 4;

    float O[16][4];
#pragma unroll
    for (int ni = 0; ni < 16; ni++)
#pragma unroll
        for (int e = 0; e < 4; e++) O[ni][e] = 0.f;
    float mrow0 = -1e30f, mrow1 = -1e30f, lrow0 = 0.f, lrow1 = 0.f;

    const int kend = q0 + F2Q;
    for (int j0 = 0; j0 < kend; j0 += F2K) {
        __syncthreads();
        for (int c = tid; c < F2K * 16; c += 256) {
            int row = c >> 4, ch = c & 15;
            size_t g = (size_t)(bS + j0 + row) * MW16 + hq + ch * 8;
            cp16(Khi + row * PQ + ch * 4, khi_g + g);
            cp16(Klo + row * PQ + ch * 4, klo_g + g);
            cp16(Vr  + row * PQ + ch * 4,
                 v16 + (size_t)(bS + j0 + row) * Pp + hq + ch * 8);
        }
        asm volatile("cp.async.commit_group;");
        asm volatile("cp.async.wait_group 0;");
        __syncthreads();

        bool active = (j0 <= q0 + wm16 + 15);
        if (active) {
            float s[4][4];
#pragma unroll
            for (int ni = 0; ni < 4; ni++)
#pragma unroll
                for (int e = 0; e < 4; e++) s[ni][e] = 0.f;

#pragma unroll
            for (int kw = 0; kw < 64; kw += 8) {
                uint32_t ahi[4], alo[4];
                ldsm4(ahi, qa_hi + kw * 4);
                ldsm4(alo, qa_lo + kw * 4);
#pragma unroll
                for (int nia = 0; nia < 2; nia++) {
                    uint32_t bh[4], bl[4];
                    ldsm4(bh, ka_hi + (nia * 16 * PQ + kw) * 4);
                    ldsm4(bl, ka_lo + (nia * 16 * PQ + kw) * 4);
                    uint32_t bh0[2] = {bh[0], bh[2]}, bh1[2] = {bh[1], bh[3]};
                    uint32_t bl0[2] = {bl[0], bl[2]}, bl1[2] = {bl[1], bl[3]};
                    mma_f16(s[2 * nia],     ahi, bh0);
                    mma_f16(s[2 * nia],     alo, bh0);
                    mma_f16(s[2 * nia],     ahi, bl0);
                    mma_f16(s[2 * nia + 1], ahi, bh1);
                    mma_f16(s[2 * nia + 1], alo, bh1);
                    mma_f16(s[2 * nia + 1], ahi, bl1);
                }
            }

            if (j0 + F2K - 1 > q0 + wm16) {
                int qlo_i = q0 + wm16 + row4;
                int qhi_i = qlo_i + 8;
#pragma unroll
                for (int ni = 0; ni < 4; ni++) {
                    int kp = j0 + ni * 8 + 2 * col4;
                    if (kp     > qlo_i) s[ni][0] = -1e30f;
                    if (kp + 1 > qlo_i) s[ni][1] = -1e30f;
                    if (kp     > qhi_i) s[ni][2] = -1e30f;
                    if (kp + 1 > qhi_i) s[ni][3] = -1e30f;
                }
            }

            float mx0 = -1e30f, mx1 = -1e30f;
#pragma unroll
            for (int ni = 0; ni < 4; ni++) {
                mx0 = fmaxf(mx0, fmaxf(s[ni][0], s[ni][1]));
                mx1 = fmaxf(mx1, fmaxf(s[ni][2], s[ni][3]));
            }
            mx0 = fmaxf(mx0, __shfl_xor_sync(0xffffffffu, mx0, 1));
            mx0 = fmaxf(mx0, __shfl_xor_sync(0xffffffffu, mx0, 2));
            mx1 = fmaxf(mx1, __shfl_xor_sync(0xffffffffu, mx1, 1));
            mx1 = fmaxf(mx1, __shfl_xor_sync(0xffffffffu, mx1, 2));
            float mn0 = fmaxf(mrow0, mx0), mn1 = fmaxf(mrow1, mx1);
            float al0 = __expf(mrow0 - mn0), al1 = __expf(mrow1 - mn1);
            mrow0 = mn0; mrow1 = mn1;

            float sum0 = 0.f, sum1 = 0.f;
            int pb0 = (wm16 + row4) * PV;
            int pb1 = (wm16 + row4 + 8) * PV;
#pragma unroll
            for (int ni = 0; ni < 4; ni++) {
                float p0 = __expf(s[ni][0] - mn0);
                float p1 = __expf(s[ni][1] - mn0);
                float p2 = __expf(s[ni][2] - mn1);
                float p3 = __expf(s[ni][3] - mn1);
                sum0 += p0 + p1; sum1 += p2 + p3;
                Ps[pb0 + ni * 4 + col4] = h2pack(p0, p1);
                Ps[pb1 + ni * 4 + col4] = h2pack(p2, p3);
            }
            lrow0 = lrow0 * al0 + sum0;
            lrow1 = lrow1 * al1 + sum1;
#pragma unroll
            for (int ni = 0; ni < 16; ni++) {
                O[ni][0] *= al0; O[ni][1] *= al0;
                O[ni][2] *= al1; O[ni][3] *= al1;
            }
            __syncwarp();

#pragma unroll
            for (int kvs = 0; kvs < 2; kvs++) {
                uint32_t a[4];
                ldsm4(a, pa_a + kvs * 8 * 4);
                uint32_t vrow = va + (uint32_t)(kvs * 16 * PQ) * 4;
#pragma unroll
                for (int nia = 0; nia < 8; nia++) {
                    uint32_t bv[4];
                    ldsm4t(bv, vrow + nia * 32);
                    mma_f16(O[2 * nia],     a, &bv[0]);
                    mma_f16(O[2 * nia + 1], a, &bv[2]);
                }
            }
        }
    }

    lrow0 += __shfl_xor_sync(0xffffffffu, lrow0, 1);
    lrow0 += __shfl_xor_sync(0xffffffffu, lrow0, 2);
    lrow1 += __shfl_xor_sync(0xffffffffu, lrow1, 1);
    lrow1 += __shfl_xor_sync(0xffffffffu, lrow1, 2);
    float inv0 = 1.f / lrow0, inv1 = 1.f / lrow1;

    size_t ob0 = (size_t)(bS + q0 + wm16 + row4) * Pp + hq;
    size_t ob1 = ob0 + (size_t)8 * Pp;
#pragma unroll
    for (int ni = 0; ni < 16; ni++) {
        int cb = ni * 8 + 2 * col4;
        *(uint32_t*)(attn16 + ob0 + cb) = h2pack(O[ni][0] * inv0, O[ni][1] * inv0);
        *(uint32_t*)(attn16 + ob1 + cb) = h2pack(O[ni][2] * inv1, O[ni][3] * inv1);
    }
}

// ---------------- tail outputs ----------------
__global__ void tails_kernel(const float* __restrict__ hs, const float* __restrict__ y1,
                             float* __restrict__ out)
{
    int i = blockIdx.x * 256 + threadIdx.x;
    size_t off1 = (size_t)Mm * Hh;
    size_t off2 = off1 + (size_t)Bb * Hh;
    if (i < Bb * Hh) {
        int b = i / Hh, hh = i % Hh;
        out[off1 + i] = hs[((size_t)b * Ss + (Ss - 1)) * Hh + hh];
    }
    if (i < Bb * H2) {
        int b = i / H2, oo = i % H2;
        out[off2 + i] = y1[((size_t)b * Ss + (Ss - 1)) * H2 + oo];
    }
}

// ---------------- launch ----------------
extern "C" void kernel_launch(void* const* d_in, const int* in_sizes, int n_in,
                              void* d_out, int out_size)
{
    (void)in_sizes; (void)n_in; (void)out_size;
    const float* hs      = (const float*)d_in[0];
    const float* freqs   = (const float*)d_in[1];
    const int*   pos     = (const int*)  d_in[2];
    const float* Wqk     = (const float*)d_in[3];
    const float* Wv      = (const float*)d_in[4];
    const float* Wo      = (const float*)d_in[5];
    const float* conv1_w = (const float*)d_in[6];
    const float* conv1_b = (const float*)d_in[7];
    const float* conv2_w = (const float*)d_in[8];
    const float* conv2_b = (const float*)d_in[9];
    const float* ln_w    = (const float*)d_in[10];
    const float* lf1c    = (const float*)d_in[11];
    const float* lf2c    = (const float*)d_in[12];
    float* out = (float*)d_out;

    float *y1, *lfout, *qk, *cosT, *sinT;
    __half *hs16, *wv16, *wqk16, *wo16, *w1a16, *w1b16, *w2a16, *w2b16;
    __half *y1h, *lf16, *v16, *attn16, *lf1c16, *lf2c16;
    __half *qhi, *qlo, *khi, *klo;
    cudaGetSymbolAddress((void**)&y1,     g_y1);
    cudaGetSymbolAddress((void**)&lfout,  g_lfout);
    cudaGetSymbolAddress((void**)&qk,     g_qk);
    cudaGetSymbolAddress((void**)&cosT,   g_cosT);
    cudaGetSymbolAddress((void**)&sinT,   g_sinT);
    cudaGetSymbolAddress((void**)&hs16,   g_hs16);
    cudaGetSymbolAddress((void**)&wv16,   g_wv16);
    cudaGetSymbolAddress((void**)&wqk16,  g_wqk16);
    cudaGetSymbolAddress((void**)&wo16,   g_wo16);
    cudaGetSymbolAddress((void**)&w1a16,  g_w1a16);
    cudaGetSymbolAddress((void**)&w1b16,  g_w1b16);
    cudaGetSymbolAddress((void**)&w2a16,  g_w2a16);
    cudaGetSymbolAddress((void**)&w2b16,  g_w2b16);
    cudaGetSymbolAddress((void**)&y1h,    g_y1h);
    cudaGetSymbolAddress((void**)&lf16,   g_lf16);
    cudaGetSymbolAddress((void**)&v16,    g_v16);
    cudaGetSymbolAddress((void**)&attn16, g_attn16);
    cudaGetSymbolAddress((void**)&lf1c16, g_lf1c16);
    cudaGetSymbolAddress((void**)&lf2c16, g_lf2c16);
    cudaGetSymbolAddress((void**)&qhi,    g_qhi);
    cudaGetSymbolAddress((void**)&qlo,    g_qlo);
    cudaGetSymbolAddress((void**)&khi,    g_khi);
    cudaGetSymbolAddress((void**)&klo,    g_klo);

    static bool attr_done = false;
    if (!attr_done) {
        cudaFuncSetAttribute(flash2_kernel,
                             cudaFuncAttributeMaxDynamicSharedMemorySize, F2_SMEM);
        cudaFuncSetAttribute(gemm_h16_kernel,
                             cudaFuncAttributeMaxDynamicSharedMemorySize, GH_SMEM);
        attr_done = true;
    }

    // 1) fp16 operand prep + cos/sin LUT
    cvt16_kernel<<<(Mm * Hh / 8 + 255) / 256, 256>>>(hs, hs16, Mm * Hh);
    cvt16_kernel<<<(Pp * Hh / 8 + 255) / 256, 256>>>(Wv, wv16, Pp * Hh);
    cvt16_kernel<<<(QKW * Hh / 8 + 255) / 256, 256>>>(Wqk, wqk16, QKW * Hh);
    cvt16_kernel<<<(Hh * Pp / 8 + 255) / 256, 256>>>(Wo, wo16, Hh * Pp);
    cvt16_kernel<<<(Bb * Hh / 8 + 255) / 256, 256>>>(lf1c, lf1c16, Bb * Hh);
    cvt16_kernel<<<(Bb * H2 / 8 + 255) / 256, 256>>>(lf2c, lf2c16, Bb * H2);
    deint16_kernel<<<(H2 * Hh + 255) / 256, 256>>>(conv1_w, w1a16, w1b16, H2 * Hh);
    deint16_kernel<<<(Hh * H2 + 255) / 256, 256>>>(conv2_w, w2a16, w2b16, Hh * H2);
    sctab_kernel<<<(MAXP * HDd) / 256, 256>>>(freqs, cosT, sinT);

    // 2) v16 = hs @ Wv^T  (fp16 only)
    gemm_h16_kernel<<<dim3(Pp / BNh, Mm / BMh), 256, GH_SMEM>>>(
        hs16, wv16, nullptr, nullptr, nullptr, v16, Pp, Hh, nullptr, nullptr);

    // 3) y1 = shift(hs) @ w1a^T + hs @ w1b^T + b1  (fp32 + fp16 mirror)
    gemm_h16_kernel<<<dim3(H2 / BNh, Mm / BMh), 256, GH_SMEM>>>(
        hs16, w1a16, hs16, w1b16, y1, y1h, H2, Hh, conv1_b, lf1c16);

    // 4) y2 = shift(y1) @ w2a^T + y1 @ w2b^T + b2
    gemm_h16_kernel<<<dim3(Hh / BNh, Mm / BMh), 256, GH_SMEM>>>(
        y1h, w2a16, y1h, w2b16, lfout, nullptr, Hh, H2, conv2_b, lf2c16);

    // 5) lf16 = rmsnorm(y2 + hs) * ln_w
    rmsnorm_kernel<<<Mm, 256>>>(lfout, hs, ln_w, lf16);

    // 6) qk = lf16 @ Wqk^T  (fp32 out)
    gemm_h16_kernel<<<dim3(QKW / BNh, Mm / BMh), 256, GH_SMEM>>>(
        lf16, wqk16, nullptr, nullptr, qk, nullptr, QKW, Hh, nullptr, nullptr);

    // 7) RoPE (LUT) -> fp16 hi/lo Q (scaled) and K
    rope3_kernel<<<Mm, 256>>>(qk, cosT, sinT, pos, qhi, qlo, khi, klo);

    // 8) fp16 flash attention -> attn16
    flash2_kernel<<<dim3(Ss / F2Q, NHh, Bb), 256, F2_SMEM>>>(
        qhi, qlo, khi, klo, v16, attn16);

    // 9) output = attn16 @ Wo^T  (fp32 out)
    gemm_h16_kernel<<<dim3(Hh / BNh, Mm / BMh), 256, GH_SMEM>>>(
        attn16, wo16, nullptr, nullptr, out, nullptr, Hh, Pp, nullptr, nullptr);

    // 10) tails
    tails_kernel<<<(Bb * Hh + 255) / 256, 256>>>(hs, y1, out);
}